// round 1
// baseline (speedup 1.0000x reference)
#include <cuda_runtime.h>
#include <cstdint>

#define BS 32
#define NANCH 90000
#define KPRE 1000
#define KPOST 300
#define NSORT 2048
#define NWORDS 16   // 16 * 64 = 1024 >= 1000 boxes
#define NMS_THR 0.7f

// ---------------- scratch (static device globals; no allocation) ----------------
__device__ float4 g_boxes[BS][KPRE];
__device__ float  g_scores[BS][KPRE];
__device__ unsigned long long g_mask[BS][KPRE][NWORDS];   // ~4 MB

// float -> order-preserving uint (ascending)
__device__ __forceinline__ unsigned flip_f(float f) {
    unsigned u = __float_as_uint(f);
    return (u & 0x80000000u) ? ~u : (u | 0x80000000u);
}
__device__ __forceinline__ float unflip_f(unsigned k) {
    unsigned u = (k & 0x80000000u) ? (k ^ 0x80000000u) : ~k;
    return __uint_as_float(u);
}

// Robustly interpret a scalar "image dim" input that may be int32/int64/float32.
__device__ __forceinline__ float read_dim(const int* p) {
    int v = *p;
    if (v > 0 && v < (1 << 24)) return (float)v;   // int32 or low word of int64
    return __int_as_float(v);                      // was actually float32 bits
}

// =============================================================================
// K1: per-batch radix-select top-1000 (on logits), exact sort, decode+clip
// =============================================================================
__global__ __launch_bounds__(1024) void select_decode_kernel(
    const float* __restrict__ logits,
    const float* __restrict__ deltas,
    const float* __restrict__ anchors,
    const int* __restrict__ p_ih,
    const int* __restrict__ p_iw)
{
    const int b   = blockIdx.x;
    const int tid = threadIdx.x;
    const float* lg = logits + (size_t)b * NANCH;

    __shared__ unsigned hist[256];
    __shared__ unsigned s_pref;
    __shared__ int      s_k;
    __shared__ unsigned s_cntA, s_cntB;
    __shared__ unsigned long long sbuf[NSORT];
    __shared__ unsigned long long ebuf[1024];

    if (tid == 0) { s_pref = 0u; s_k = KPRE; }

    // ---- 4 MSB-first radix passes: find exact threshold key T ----
    for (int pass = 0; pass < 4; ++pass) {
        const int shift = 24 - 8 * pass;
        if (tid < 256) hist[tid] = 0u;
        __syncthreads();
        const unsigned pref  = s_pref;
        const unsigned hmask = (pass == 0) ? 0u : (0xFFFFFFFFu << (32 - 8 * pass));
        for (int i = tid; i < NANCH; i += 1024) {
            unsigned key = flip_f(lg[i]);
            if ((key & hmask) == pref)
                atomicAdd(&hist[(key >> shift) & 0xFFu], 1u);
        }
        __syncthreads();
        if (tid == 0) {
            int k = s_k;
            unsigned acc = 0u;
            int bsel = 0;
            for (int bin = 255; bin >= 0; --bin) {
                unsigned c = hist[bin];
                if (acc + c >= (unsigned)k) { bsel = bin; break; }
                acc += c;
            }
            s_pref = pref | ((unsigned)bsel << shift);
            s_k    = k - (int)acc;
        }
        __syncthreads();
    }
    const unsigned T = s_pref;          // exact 1000th-largest key

    // ---- gather: strictly-greater plus equal-to-threshold candidates ----
    if (tid == 0) { s_cntA = 0u; s_cntB = 0u; }
    for (int i = tid; i < NSORT; i += 1024) sbuf[i] = 0ull;
    __syncthreads();
    for (int i = tid; i < NANCH; i += 1024) {
        unsigned key = flip_f(lg[i]);
        if (key > T) {
            unsigned p = atomicAdd(&s_cntA, 1u);
            sbuf[p] = ((unsigned long long)key << 32) | (unsigned)(~(unsigned)i);
        } else if (key == T) {
            unsigned p = atomicAdd(&s_cntB, 1u);
            if (p < 1024u)
                ebuf[p] = ((unsigned long long)key << 32) | (unsigned)(~(unsigned)i);
        }
    }
    __syncthreads();
    const unsigned cntA = s_cntA;                 // = KPRE - (#equals needed)
    const unsigned cntB = min(s_cntB, 1024u);
    for (unsigned i = tid; i < cntB; i += 1024) {
        unsigned p = cntA + i;
        if (p < NSORT) sbuf[p] = ebuf[i];
    }
    __syncthreads();

    // ---- bitonic sort 2048 composites, descending ((score desc, idx asc)) ----
    for (int size = 2; size <= NSORT; size <<= 1) {
        for (int stride = size >> 1; stride > 0; stride >>= 1) {
            __syncthreads();
            int i = 2 * tid - (tid & (stride - 1));
            int j = i + stride;
            unsigned long long a = sbuf[i];
            unsigned long long c = sbuf[j];
            bool desc = ((i & size) == 0);
            if ((a < c) == desc) { sbuf[i] = c; sbuf[j] = a; }
        }
    }
    __syncthreads();

    // ---- decode + clip top-1000 ----
    const float fw = read_dim(p_iw);
    const float fh = read_dim(p_ih);
    if (tid < KPRE) {
        unsigned long long comp = sbuf[tid];
        unsigned idx = ~(unsigned)(comp & 0xFFFFFFFFull);
        unsigned key = (unsigned)(comp >> 32);
        float logit = unflip_f(key);
        float score = 1.0f / (1.0f + expf(-logit));

        const float* d = deltas  + ((size_t)b * NANCH + idx) * 4;
        const float* a = anchors + (size_t)idx * 4;
        float a0 = a[0], a1 = a[1], a2 = a[2], a3 = a[3];
        float aw  = a2 - a0;
        float ah  = a3 - a1;
        float acx = a0 + 0.5f * aw;
        float acy = a1 + 0.5f * ah;
        float cx = d[0] * aw + acx;
        float cy = d[1] * ah + acy;
        float w  = expf(d[2]) * aw;
        float h  = expf(d[3]) * ah;
        float x1 = fminf(fmaxf(cx - 0.5f * w, 0.0f), fw);
        float y1 = fminf(fmaxf(cy - 0.5f * h, 0.0f), fh);
        float x2 = fminf(fmaxf(cx + 0.5f * w, 0.0f), fw);
        float y2 = fminf(fmaxf(cy + 0.5f * h, 0.0f), fh);
        g_boxes[b][tid]  = make_float4(x1, y1, x2, y2);
        g_scores[b][tid] = score;
    }
}

// =============================================================================
// K2: IoU suppression bitmask. Bit (i, j) set iff j > i and IoU(i,j) > 0.7
// grid (colBlocks=16, rowBlocks=16, BS), block 64 threads
// =============================================================================
__global__ __launch_bounds__(64) void nms_mask_kernel()
{
    const int b  = blockIdx.z;
    const int rb = blockIdx.y;
    const int cb = blockIdx.x;
    const int i  = rb * 64 + threadIdx.x;

    __shared__ float4 cbox[64];
    __shared__ float  carea[64];
    const int cbase = cb * 64;
    const int ncol  = min(64, KPRE - cbase);
    if (threadIdx.x < ncol) {
        float4 bx = g_boxes[b][cbase + threadIdx.x];
        cbox[threadIdx.x]  = bx;
        carea[threadIdx.x] = (bx.z - bx.x) * (bx.w - bx.y);
    }
    __syncthreads();
    if (i >= KPRE) return;

    unsigned long long bits = 0ull;
    if (cbase + 63 > i) {                    // block contains some j > i
        float4 bi = g_boxes[b][i];
        float  ai = (bi.z - bi.x) * (bi.w - bi.y);
        #pragma unroll 4
        for (int j = 0; j < ncol; ++j) {
            int jj = cbase + j;
            if (jj <= i) continue;
            float4 bj = cbox[j];
            float lx = fmaxf(bi.x, bj.x);
            float ly = fmaxf(bi.y, bj.y);
            float rx = fminf(bi.z, bj.z);
            float ry = fminf(bi.w, bj.w);
            float w  = fmaxf(rx - lx, 0.0f);
            float h  = fmaxf(ry - ly, 0.0f);
            float inter = w * h;
            float iou = inter / (ai + carea[j] - inter + 1e-12f);
            if (iou > NMS_THR) bits |= (1ull << j);
        }
    }
    g_mask[b][i][cb] = bits;
}

// =============================================================================
// K3: sequential greedy scan (iterations == kept count, early exit at 300),
//     then compact + write output. One CTA per batch; mask preloaded to SMEM.
// =============================================================================
extern __shared__ unsigned long long s_mask_dyn[];   // KPRE * NWORDS words = 128 KB

__global__ __launch_bounds__(512) void nms_scan_out_kernel(float* __restrict__ out)
{
    const int b   = blockIdx.x;
    const int tid = threadIdx.x;

    __shared__ unsigned long long s_remv[NWORDS];
    __shared__ int s_list[KPOST];
    __shared__ int s_kept;

    // preload this batch's full mask into shared (coalesced)
    const unsigned long long* gm = &g_mask[b][0][0];
    for (int i = tid; i < KPRE * NWORDS; i += blockDim.x) s_mask_dyn[i] = gm[i];
    if (tid < NWORDS) s_remv[tid] = 0ull;
    if (tid == 0) s_kept = 0;
    __syncthreads();

    if (tid < 32) {
        const int lane = tid;
        int kept = 0;
        for (int w = 0; w < NWORDS && kept < KPOST; ++w) {
            unsigned long long valid =
                (w == NWORDS - 1) ? ((1ull << (KPRE - 64 * (NWORDS - 1))) - 1ull)
                                  : ~0ull;
            for (;;) {
                unsigned long long avail = (~s_remv[w]) & valid;
                if (!avail) break;
                int bit = __ffsll((long long)avail) - 1;
                int i = w * 64 + bit;
                valid &= ~(1ull << bit);
                if (lane == 0) s_list[kept] = i;
                kept++;
                if (kept == KPOST) break;
                if (lane < NWORDS)
                    s_remv[lane] |= s_mask_dyn[i * NWORDS + lane];
                __syncwarp();
            }
        }
        if (lane == 0) s_kept = kept;
    }
    __syncthreads();

    const int kept = s_kept;
    float* ob = out + (size_t)b * KPOST * 5;
    for (int r = tid; r < KPOST; r += blockDim.x) {
        if (r < kept) {
            int i = s_list[r];
            float4 bx = g_boxes[b][i];
            float  sc = g_scores[b][i];
            ob[r * 5 + 0] = bx.x;
            ob[r * 5 + 1] = bx.y;
            ob[r * 5 + 2] = bx.z;
            ob[r * 5 + 3] = bx.w;
            ob[r * 5 + 4] = sc;
        } else {
            ob[r * 5 + 0] = 0.0f;
            ob[r * 5 + 1] = 0.0f;
            ob[r * 5 + 2] = 0.0f;
            ob[r * 5 + 3] = 0.0f;
            ob[r * 5 + 4] = 0.0f;
        }
    }
}

// =============================================================================
extern "C" void kernel_launch(void* const* d_in, const int* in_sizes, int n_in,
                              void* d_out, int out_size)
{
    const float* logits  = (const float*)d_in[0];
    const float* deltas  = (const float*)d_in[1];
    const float* anchors = (const float*)d_in[2];
    const int*   p_ih    = (const int*)d_in[3];
    const int*   p_iw    = (const int*)d_in[4];

    // opt-in shared memory for the scan kernel (idempotent; host-side, capture-safe)
    cudaFuncSetAttribute(nms_scan_out_kernel,
                         cudaFuncAttributeMaxDynamicSharedMemorySize,
                         KPRE * NWORDS * (int)sizeof(unsigned long long));

    select_decode_kernel<<<BS, 1024>>>(logits, deltas, anchors, p_ih, p_iw);
    nms_mask_kernel<<<dim3(NWORDS, NWORDS, BS), 64>>>();
    nms_scan_out_kernel<<<BS, 512,
                          KPRE * NWORDS * (int)sizeof(unsigned long long)>>>(
        (float*)d_out);
}

// round 2
// speedup vs baseline: 1.2089x; 1.2089x over previous
#include <cuda_runtime.h>
#include <cstdint>

#define BS 32
#define NANCH 90000
#define KPRE 1000
#define KPOST 300
#define NWORDS 16            // 16*64 = 1024 >= 1000
#define NMS_THR 0.7f

#define HBITS 14
#define NBINS (1 << HBITS)   // 16384
#define HSHIFT (32 - HBITS)  // 18
#define NCHUNK 5
#define CHUNK 18000          // 5 * 18000 = 90000
#define CANDCAP 4096

typedef unsigned long long u64;

// ---------------- scratch (static device globals; no allocation) ----------------
__device__ unsigned g_hist[BS][NBINS];      // 2 MB
__device__ int      g_thresh[BS];
__device__ unsigned g_cnt[BS];
__device__ u64      g_cand[BS][CANDCAP];    // 1 MB
__device__ float4   g_boxes[BS][KPRE];
__device__ float    g_scores[BS][KPRE];
__device__ u64      g_mask[BS][KPRE][NWORDS];   // 4 MB, zero-init; lower-tri never written

// float -> order-preserving uint (ascending)
__device__ __forceinline__ unsigned flip_f(float f) {
    unsigned u = __float_as_uint(f);
    return (u & 0x80000000u) ? ~u : (u | 0x80000000u);
}
__device__ __forceinline__ float unflip_f(unsigned k) {
    unsigned u = (k & 0x80000000u) ? (k ^ 0x80000000u) : ~k;
    return __uint_as_float(u);
}
__device__ __forceinline__ float read_dim(const int* p) {
    int v = *p;
    if (v > 0 && v < (1 << 24)) return (float)v;
    return __int_as_float(v);
}

// =============================================================================
// K0: zero histogram + counters
// =============================================================================
__global__ __launch_bounds__(1024) void zero_kernel()
{
    int idx = blockIdx.x * 1024 + threadIdx.x;
    const int total = BS * NBINS;
    if (idx < total) ((unsigned*)g_hist)[idx] = 0u;
    if (idx < BS) g_cnt[idx] = 0u;
}

// =============================================================================
// K1a: per-batch 14-bit histogram of flipped logits. grid (NCHUNK, BS)
// =============================================================================
__global__ __launch_bounds__(1024) void hist_kernel(const float* __restrict__ logits)
{
    extern __shared__ unsigned sh_hist[];   // NBINS
    const int b   = blockIdx.y;
    const int tid = threadIdx.x;
    const float* lg = logits + (size_t)b * NANCH;

    for (int i = tid; i < NBINS; i += 1024) sh_hist[i] = 0u;
    __syncthreads();

    const int start = blockIdx.x * CHUNK;
    const int end   = min(start + CHUNK, NANCH);
    for (int i = start + tid; i < end; i += 1024)
        atomicAdd(&sh_hist[flip_f(lg[i]) >> HSHIFT], 1u);
    __syncthreads();

    for (int i = tid; i < NBINS; i += 1024) {
        unsigned v = sh_hist[i];
        if (v) atomicAdd(&g_hist[b][i], v);
    }
}

// =============================================================================
// K1b: per-batch threshold-bin selection (suffix scan over 16384 bins)
// =============================================================================
__global__ __launch_bounds__(1024) void thresh_kernel()
{
    const int b   = blockIdx.x;
    const int tid = threadIdx.x;
    __shared__ unsigned suf[1024];
    const unsigned* h = g_hist[b];

    const int base = tid * 16;
    unsigned s = 0;
    #pragma unroll
    for (int k = 0; k < 16; ++k) s += h[base + k];
    suf[tid] = s;
    __syncthreads();

    // Hillis-Steele suffix scan
    for (int off = 1; off < 1024; off <<= 1) {
        unsigned v = (tid + off < 1024) ? suf[tid + off] : 0u;
        __syncthreads();
        suf[tid] += v;
        __syncthreads();
    }

    unsigned mine  = suf[tid];
    unsigned above = (tid < 1023) ? suf[tid + 1] : 0u;
    if (mine >= KPRE && above < KPRE) {
        unsigned acc = above;
        int t = base;
        for (int k = 15; k >= 0; --k) {
            acc += h[base + k];
            if (acc >= KPRE) { t = base + k; break; }
        }
        g_thresh[b] = t;
    }
}

// =============================================================================
// K1c: gather candidates with bin >= threshold bin. grid (NCHUNK, BS)
// =============================================================================
__global__ __launch_bounds__(1024) void gather_kernel(const float* __restrict__ logits)
{
    const int b    = blockIdx.y;
    const int tid  = threadIdx.x;
    const int lane = tid & 31;
    const float* lg = logits + (size_t)b * NANCH;
    const unsigned t = (unsigned)g_thresh[b];

    const int start = blockIdx.x * CHUNK;
    const int end   = min(start + CHUNK, NANCH);
    for (int base = start; base < end; base += 1024) {
        int i = base + tid;
        unsigned key = 0u;
        bool pred = false;
        if (i < end) {
            key = flip_f(lg[i]);
            pred = (key >> HSHIFT) >= t;
        }
        unsigned m = __ballot_sync(0xFFFFFFFFu, pred);
        if (pred) {
            int leader = __ffs(m) - 1;
            int rank   = __popc(m & ((1u << lane) - 1u));
            unsigned pos = 0u;
            if (lane == leader) pos = atomicAdd(&g_cnt[b], (unsigned)__popc(m));
            pos = __shfl_sync(m, pos, leader);
            unsigned p = pos + (unsigned)rank;
            if (p < CANDCAP)
                g_cand[b][p] = ((u64)key << 32) | (unsigned)(~(unsigned)i);
        }
    }
}

// =============================================================================
// K1d: bitonic sort candidates (desc), take top-1000, decode+clip
// =============================================================================
__global__ __launch_bounds__(1024) void sort_decode_kernel(
    const float* __restrict__ deltas,
    const float* __restrict__ anchors,
    const int* __restrict__ p_ih,
    const int* __restrict__ p_iw)
{
    const int b   = blockIdx.x;
    const int tid = threadIdx.x;
    __shared__ u64 sbuf[CANDCAP];

    const int n = min((int)g_cnt[b], CANDCAP);
    const int S = (n <= 2048) ? 2048 : CANDCAP;

    for (int i = tid; i < S; i += 1024)
        sbuf[i] = (i < n) ? g_cand[b][i] : 0ull;
    __syncthreads();

    for (int size = 2; size <= S; size <<= 1) {
        for (int stride = size >> 1; stride > 0; stride >>= 1) {
            for (int k = tid; k < (S >> 1); k += 1024) {
                int i = 2 * k - (k & (stride - 1));
                int j = i + stride;
                u64 a = sbuf[i];
                u64 c = sbuf[j];
                bool desc = ((i & size) == 0);
                if ((a < c) == desc) { sbuf[i] = c; sbuf[j] = a; }
            }
            __syncthreads();
        }
    }

    const float fw = read_dim(p_iw);
    const float fh = read_dim(p_ih);
    if (tid < KPRE) {
        u64 comp = sbuf[tid];
        unsigned idx = ~(unsigned)(comp & 0xFFFFFFFFull);
        unsigned key = (unsigned)(comp >> 32);
        float logit = unflip_f(key);
        float score = 1.0f / (1.0f + expf(-logit));

        const float* d = deltas  + ((size_t)b * NANCH + idx) * 4;
        const float* a = anchors + (size_t)idx * 4;
        float a0 = a[0], a1 = a[1], a2 = a[2], a3 = a[3];
        float aw  = a2 - a0;
        float ah  = a3 - a1;
        float acx = a0 + 0.5f * aw;
        float acy = a1 + 0.5f * ah;
        float cx = d[0] * aw + acx;
        float cy = d[1] * ah + acy;
        float w  = expf(d[2]) * aw;
        float h  = expf(d[3]) * ah;
        float x1 = fminf(fmaxf(cx - 0.5f * w, 0.0f), fw);
        float y1 = fminf(fmaxf(cy - 0.5f * h, 0.0f), fh);
        float x2 = fminf(fmaxf(cx + 0.5f * w, 0.0f), fw);
        float y2 = fminf(fmaxf(cy + 0.5f * h, 0.0f), fh);
        g_boxes[b][tid]  = make_float4(x1, y1, x2, y2);
        g_scores[b][tid] = score;
    }
}

// =============================================================================
// K2: IoU bitmask, upper-triangular blocks only. grid (136, BS), 64 threads
// =============================================================================
__global__ __launch_bounds__(64) void nms_mask_kernel()
{
    const int b = blockIdx.y;
    // decode triangular (rb, cb) with cb >= rb from linear index
    int p = blockIdx.x;
    int rb = 0, rem = NWORDS;
    while (p >= rem) { p -= rem; ++rb; --rem; }
    const int cb = rb + p;
    const int i  = rb * 64 + threadIdx.x;

    __shared__ float4 cbox[64];
    __shared__ float  carea[64];
    const int cbase = cb * 64;
    const int ncol  = min(64, KPRE - cbase);
    if (threadIdx.x < ncol) {
        float4 bx = g_boxes[b][cbase + threadIdx.x];
        cbox[threadIdx.x]  = bx;
        carea[threadIdx.x] = (bx.z - bx.x) * (bx.w - bx.y);
    }
    __syncthreads();
    if (i >= KPRE) return;

    u64 bits = 0ull;
    float4 bi = g_boxes[b][i];
    float  ai = (bi.z - bi.x) * (bi.w - bi.y);
    #pragma unroll 4
    for (int j = 0; j < ncol; ++j) {
        int jj = cbase + j;
        if (jj <= i) continue;
        float4 bj = cbox[j];
        float lx = fmaxf(bi.x, bj.x);
        float ly = fmaxf(bi.y, bj.y);
        float rx = fminf(bi.z, bj.z);
        float ry = fminf(bi.w, bj.w);
        float w  = fmaxf(rx - lx, 0.0f);
        float h  = fmaxf(ry - ly, 0.0f);
        float inter = w * h;
        float iou = inter / (ai + carea[j] - inter + 1e-12f);
        if (iou > NMS_THR) bits |= (1ull << j);
    }
    g_mask[b][i][cb] = bits;
}

// =============================================================================
// K3: sequential greedy scan with register-resident removal mask, then output
// =============================================================================
__global__ __launch_bounds__(1024) void nms_scan_out_kernel(float* __restrict__ out)
{
    extern __shared__ u64 sm[];          // KPRE * NWORDS = 16000 words (128 KB)
    const int b   = blockIdx.x;
    const int tid = threadIdx.x;

    __shared__ int s_list[KPOST];
    __shared__ int s_kept;

    const u64* gm = &g_mask[b][0][0];
    for (int i = tid; i < KPRE * NWORDS; i += 1024) sm[i] = gm[i];
    __syncthreads();

    if (tid == 0) {
        u64 remv[NWORDS];
        #pragma unroll
        for (int k = 0; k < NWORDS; ++k) remv[k] = 0ull;
        int kept = 0;
        #pragma unroll
        for (int w = 0; w < NWORDS; ++w) {
            if (kept >= KPOST) break;
            const u64 valid = (w == NWORDS - 1)
                ? ((1ull << (KPRE - 64 * (NWORDS - 1))) - 1ull) : ~0ull;
            u64 avail = (~remv[w]) & valid;
            while (avail) {
                int bit = __ffsll((long long)avail) - 1;
                int i = w * 64 + bit;
                s_list[kept++] = i;
                if (kept == KPOST) break;
                const u64* row = &sm[i * NWORDS];
                #pragma unroll
                for (int k = 0; k < NWORDS; ++k) remv[k] |= row[k];
                u64 high = (bit == 63) ? 0ull : (~0ull << (bit + 1));
                avail = (~remv[w]) & valid & high;
            }
        }
        s_kept = kept;
    }
    __syncthreads();

    const int kept = s_kept;
    float* ob = out + (size_t)b * KPOST * 5;
    for (int r = tid; r < KPOST; r += 1024) {
        if (r < kept) {
            int i = s_list[r];
            float4 bx = g_boxes[b][i];
            float  sc = g_scores[b][i];
            ob[r * 5 + 0] = bx.x;
            ob[r * 5 + 1] = bx.y;
            ob[r * 5 + 2] = bx.z;
            ob[r * 5 + 3] = bx.w;
            ob[r * 5 + 4] = sc;
        } else {
            ob[r * 5 + 0] = 0.0f;
            ob[r * 5 + 1] = 0.0f;
            ob[r * 5 + 2] = 0.0f;
            ob[r * 5 + 3] = 0.0f;
            ob[r * 5 + 4] = 0.0f;
        }
    }
}

// =============================================================================
extern "C" void kernel_launch(void* const* d_in, const int* in_sizes, int n_in,
                              void* d_out, int out_size)
{
    const float* logits  = (const float*)d_in[0];
    const float* deltas  = (const float*)d_in[1];
    const float* anchors = (const float*)d_in[2];
    const int*   p_ih    = (const int*)d_in[3];
    const int*   p_iw    = (const int*)d_in[4];

    cudaFuncSetAttribute(hist_kernel,
                         cudaFuncAttributeMaxDynamicSharedMemorySize,
                         NBINS * (int)sizeof(unsigned));
    cudaFuncSetAttribute(nms_scan_out_kernel,
                         cudaFuncAttributeMaxDynamicSharedMemorySize,
                         KPRE * NWORDS * (int)sizeof(u64));

    zero_kernel<<<(BS * NBINS + 1023) / 1024, 1024>>>();
    hist_kernel<<<dim3(NCHUNK, BS), 1024, NBINS * sizeof(unsigned)>>>(logits);
    thresh_kernel<<<BS, 1024>>>();
    gather_kernel<<<dim3(NCHUNK, BS), 1024>>>(logits);
    sort_decode_kernel<<<BS, 1024>>>(deltas, anchors, p_ih, p_iw);
    nms_mask_kernel<<<dim3(NWORDS * (NWORDS + 1) / 2, BS), 64>>>();
    nms_scan_out_kernel<<<BS, 1024, KPRE * NWORDS * sizeof(u64)>>>((float*)d_out);
}

// round 3
// speedup vs baseline: 1.4390x; 1.1903x over previous
#include <cuda_runtime.h>
#include <cstdint>

#define BS 32
#define NANCH 90000
#define NVEC (NANCH / 4)     // 22500 float4 per batch
#define KPRE 1000
#define KPOST 300
#define NWORDS 16            // 16*64 = 1024 >= 1000
#define NMS_THR 0.7f

#define HBITS 13
#define NBINS (1 << HBITS)   // 8192
#define HSHIFT (32 - HBITS)  // 19
#define CANDCAP 4096

typedef unsigned long long u64;

// ---------------- scratch (static device globals; no allocation) ----------------
__device__ float4 g_boxes[BS][KPRE];
__device__ float  g_scores[BS][KPRE];
__device__ u64    g_mask[BS][KPRE][NWORDS];  // upper-tri words overwritten each run;
                                             // lower-tri words stay zero forever (never read harmfully)

// float -> order-preserving uint (ascending)
__device__ __forceinline__ unsigned flip_f(float f) {
    unsigned u = __float_as_uint(f);
    return (u & 0x80000000u) ? ~u : (u | 0x80000000u);
}
__device__ __forceinline__ float unflip_f(unsigned k) {
    unsigned u = (k & 0x80000000u) ? (k ^ 0x80000000u) : ~k;
    return __uint_as_float(u);
}
__device__ __forceinline__ float read_dim(const int* p) {
    int v = *p;
    if (v > 0 && v < (1 << 24)) return (float)v;
    return __int_as_float(v);
}

// =============================================================================
// K1 (fused): histogram -> threshold bin -> gather -> bitonic sort -> decode
// One CTA per batch, 1024 threads, float4 sweeps, everything in shared memory.
// =============================================================================
extern __shared__ unsigned s_dyn[];   // aliased region, >= max(NBINS*4, CANDCAP*8)

__global__ __launch_bounds__(1024) void select_decode_fused(
    const float* __restrict__ logits,
    const float* __restrict__ deltas,
    const float* __restrict__ anchors,
    const int* __restrict__ p_ih,
    const int* __restrict__ p_iw)
{
    const int b   = blockIdx.x;
    const int tid = threadIdx.x;

    unsigned* hist = s_dyn;                          // NBINS u32 (32 KB)
    u64*      cand = (u64*)s_dyn;                    // CANDCAP u64 (32 KB), reused after hist
    __shared__ unsigned s_suf[1024];
    __shared__ unsigned s_t;
    __shared__ unsigned s_cnt;

    const float4* lg4 = (const float4*)(logits + (size_t)b * NANCH);

    // ---- pass 1: 13-bit histogram in shared ----
    for (int i = tid; i < NBINS; i += 1024) hist[i] = 0u;
    if (tid == 0) s_cnt = 0u;
    __syncthreads();

    for (int i = tid; i < NVEC; i += 1024) {
        float4 v = lg4[i];
        atomicAdd(&hist[flip_f(v.x) >> HSHIFT], 1u);
        atomicAdd(&hist[flip_f(v.y) >> HSHIFT], 1u);
        atomicAdd(&hist[flip_f(v.z) >> HSHIFT], 1u);
        atomicAdd(&hist[flip_f(v.w) >> HSHIFT], 1u);
    }
    __syncthreads();

    // ---- threshold bin: largest t with suffix_count(t) >= KPRE ----
    {
        const int base = tid * (NBINS / 1024);       // 8 bins per thread
        unsigned s = 0;
        #pragma unroll
        for (int k = 0; k < NBINS / 1024; ++k) s += hist[base + k];
        s_suf[tid] = s;
        __syncthreads();
        for (int off = 1; off < 1024; off <<= 1) {
            unsigned v = (tid + off < 1024) ? s_suf[tid + off] : 0u;
            __syncthreads();
            s_suf[tid] += v;
            __syncthreads();
        }
        unsigned mine  = s_suf[tid];
        unsigned above = (tid < 1023) ? s_suf[tid + 1] : 0u;
        if (mine >= KPRE && above < KPRE) {
            unsigned acc = above;
            int t = base;
            #pragma unroll
            for (int k = NBINS / 1024 - 1; k >= 0; --k) {
                acc += hist[base + k];
                if (acc >= KPRE) { t = base + k; break; }
            }
            s_t = (unsigned)t;
        }
    }
    __syncthreads();
    const unsigned t = s_t;
    __syncthreads();            // everyone has read s_t / hist before cand aliasing

    // ---- pass 2: gather candidates with bin >= t into shared (aliased) ----
    for (int i = tid; i < NVEC; i += 1024) {
        float4 v = lg4[i];
        unsigned k0 = flip_f(v.x);
        unsigned k1 = flip_f(v.y);
        unsigned k2 = flip_f(v.z);
        unsigned k3 = flip_f(v.w);
        const int i0 = 4 * i;
        if ((k0 >> HSHIFT) >= t) {
            unsigned p = atomicAdd(&s_cnt, 1u);
            if (p < CANDCAP) cand[p] = ((u64)k0 << 32) | (unsigned)(~(unsigned)(i0));
        }
        if ((k1 >> HSHIFT) >= t) {
            unsigned p = atomicAdd(&s_cnt, 1u);
            if (p < CANDCAP) cand[p] = ((u64)k1 << 32) | (unsigned)(~(unsigned)(i0 + 1));
        }
        if ((k2 >> HSHIFT) >= t) {
            unsigned p = atomicAdd(&s_cnt, 1u);
            if (p < CANDCAP) cand[p] = ((u64)k2 << 32) | (unsigned)(~(unsigned)(i0 + 2));
        }
        if ((k3 >> HSHIFT) >= t) {
            unsigned p = atomicAdd(&s_cnt, 1u);
            if (p < CANDCAP) cand[p] = ((u64)k3 << 32) | (unsigned)(~(unsigned)(i0 + 3));
        }
    }
    __syncthreads();

    const int n = min((int)s_cnt, CANDCAP);
    const int S = (n <= 2048) ? 2048 : CANDCAP;
    for (int i = n + tid; i < S; i += 1024) cand[i] = 0ull;
    __syncthreads();

    // ---- bitonic sort composites descending ((score desc, idx asc)) ----
    for (int size = 2; size <= S; size <<= 1) {
        for (int stride = size >> 1; stride > 0; stride >>= 1) {
            for (int k = tid; k < (S >> 1); k += 1024) {
                int i = 2 * k - (k & (stride - 1));
                int j = i + stride;
                u64 a = cand[i];
                u64 c = cand[j];
                bool desc = ((i & size) == 0);
                if ((a < c) == desc) { cand[i] = c; cand[j] = a; }
            }
            __syncthreads();
        }
    }

    // ---- decode + clip top-1000 ----
    const float fw = read_dim(p_iw);
    const float fh = read_dim(p_ih);
    if (tid < KPRE) {
        u64 comp = cand[tid];
        unsigned idx = ~(unsigned)(comp & 0xFFFFFFFFull);
        unsigned key = (unsigned)(comp >> 32);
        float logit = unflip_f(key);
        float score = 1.0f / (1.0f + expf(-logit));

        float4 d = ((const float4*)deltas)[(size_t)b * NANCH + idx];
        float4 a = ((const float4*)anchors)[idx];
        float aw  = a.z - a.x;
        float ah  = a.w - a.y;
        float acx = a.x + 0.5f * aw;
        float acy = a.y + 0.5f * ah;
        float cx = d.x * aw + acx;
        float cy = d.y * ah + acy;
        float w  = expf(d.z) * aw;
        float h  = expf(d.w) * ah;
        float x1 = fminf(fmaxf(cx - 0.5f * w, 0.0f), fw);
        float y1 = fminf(fmaxf(cy - 0.5f * h, 0.0f), fh);
        float x2 = fminf(fmaxf(cx + 0.5f * w, 0.0f), fw);
        float y2 = fminf(fmaxf(cy + 0.5f * h, 0.0f), fh);
        g_boxes[b][tid]  = make_float4(x1, y1, x2, y2);
        g_scores[b][tid] = score;
    }
}

// =============================================================================
// K2: IoU bitmask, upper-triangular blocks only. grid (136, BS), 64 threads
// =============================================================================
__global__ __launch_bounds__(64) void nms_mask_kernel()
{
    const int b = blockIdx.y;
    int p = blockIdx.x;
    int rb = 0, rem = NWORDS;
    while (p >= rem) { p -= rem; ++rb; --rem; }
    const int cb = rb + p;
    const int i  = rb * 64 + threadIdx.x;

    __shared__ float4 cbox[64];
    __shared__ float  carea[64];
    const int cbase = cb * 64;
    const int ncol  = min(64, KPRE - cbase);
    if (threadIdx.x < ncol) {
        float4 bx = g_boxes[b][cbase + threadIdx.x];
        cbox[threadIdx.x]  = bx;
        carea[threadIdx.x] = (bx.z - bx.x) * (bx.w - bx.y);
    }
    __syncthreads();
    if (i >= KPRE) return;

    u64 bits = 0ull;
    float4 bi = g_boxes[b][i];
    float  ai = (bi.z - bi.x) * (bi.w - bi.y);
    #pragma unroll 4
    for (int j = 0; j < ncol; ++j) {
        int jj = cbase + j;
        if (jj <= i) continue;
        float4 bj = cbox[j];
        float lx = fmaxf(bi.x, bj.x);
        float ly = fmaxf(bi.y, bj.y);
        float rx = fminf(bi.z, bj.z);
        float ry = fminf(bi.w, bj.w);
        float w  = fmaxf(rx - lx, 0.0f);
        float h  = fmaxf(ry - ly, 0.0f);
        float inter = w * h;
        float iou = inter / (ai + carea[j] - inter + 1e-12f);
        if (iou > NMS_THR) bits |= (1ull << j);
    }
    g_mask[b][i][cb] = bits;
}

// =============================================================================
// K3: sequential greedy scan with register-resident removal mask, then output
// =============================================================================
extern __shared__ u64 s_mask[];   // KPRE*NWORDS u64 = 128 KB

__global__ __launch_bounds__(1024) void nms_scan_out_kernel(float* __restrict__ out)
{
    const int b   = blockIdx.x;
    const int tid = threadIdx.x;

    __shared__ int s_list[KPOST];
    __shared__ int s_kept;

    const u64* gm = &g_mask[b][0][0];
    for (int i = tid; i < KPRE * NWORDS; i += 1024) s_mask[i] = gm[i];
    __syncthreads();

    if (tid == 0) {
        u64 remv[NWORDS];
        #pragma unroll
        for (int k = 0; k < NWORDS; ++k) remv[k] = 0ull;
        int kept = 0;
        #pragma unroll
        for (int w = 0; w < NWORDS; ++w) {
            if (kept >= KPOST) break;
            const u64 valid = (w == NWORDS - 1)
                ? ((1ull << (KPRE - 64 * (NWORDS - 1))) - 1ull) : ~0ull;
            u64 avail = (~remv[w]) & valid;
            while (avail) {
                int bit = __ffsll((long long)avail) - 1;
                int i = w * 64 + bit;
                s_list[kept++] = i;
                if (kept == KPOST) break;
                const u64* row = &s_mask[i * NWORDS];
                #pragma unroll
                for (int k = 0; k < NWORDS; ++k) remv[k] |= row[k];
                u64 high = (bit == 63) ? 0ull : (~0ull << (bit + 1));
                avail = (~remv[w]) & valid & high;
            }
        }
        s_kept = kept;
    }
    __syncthreads();

    const int kept = s_kept;
    float* ob = out + (size_t)b * KPOST * 5;
    for (int r = tid; r < KPOST; r += 1024) {
        if (r < kept) {
            int i = s_list[r];
            float4 bx = g_boxes[b][i];
            float  sc = g_scores[b][i];
            ob[r * 5 + 0] = bx.x;
            ob[r * 5 + 1] = bx.y;
            ob[r * 5 + 2] = bx.z;
            ob[r * 5 + 3] = bx.w;
            ob[r * 5 + 4] = sc;
        } else {
            ob[r * 5 + 0] = 0.0f;
            ob[r * 5 + 1] = 0.0f;
            ob[r * 5 + 2] = 0.0f;
            ob[r * 5 + 3] = 0.0f;
            ob[r * 5 + 4] = 0.0f;
        }
    }
}

// =============================================================================
extern "C" void kernel_launch(void* const* d_in, const int* in_sizes, int n_in,
                              void* d_out, int out_size)
{
    const float* logits  = (const float*)d_in[0];
    const float* deltas  = (const float*)d_in[1];
    const float* anchors = (const float*)d_in[2];
    const int*   p_ih    = (const int*)d_in[3];
    const int*   p_iw    = (const int*)d_in[4];

    const int fusedSmem = CANDCAP * (int)sizeof(u64);   // 32 KB (>= NBINS*4)
    cudaFuncSetAttribute(select_decode_fused,
                         cudaFuncAttributeMaxDynamicSharedMemorySize, fusedSmem);
    cudaFuncSetAttribute(nms_scan_out_kernel,
                         cudaFuncAttributeMaxDynamicSharedMemorySize,
                         KPRE * NWORDS * (int)sizeof(u64));

    select_decode_fused<<<BS, 1024, fusedSmem>>>(logits, deltas, anchors, p_ih, p_iw);
    nms_mask_kernel<<<dim3(NWORDS * (NWORDS + 1) / 2, BS), 64>>>();
    nms_scan_out_kernel<<<BS, 1024, KPRE * NWORDS * sizeof(u64)>>>((float*)d_out);
}

// round 7
// speedup vs baseline: 1.8308x; 1.2723x over previous
#include <cuda_runtime.h>
#include <cstdint>

#define BS 32
#define NANCH 90000
#define NVEC (NANCH / 4)       // 22500 float4 per batch
#define NQ 4                   // quarters per batch
#define QVEC (NVEC / NQ)       // 5625 float4 per quarter
#define KPRE 1000
#define KPOST 300
#define NWORDS 16              // 16*64 = 1024 >= 1000
#define NMS_THR 0.7f

#define HBITS 13
#define NBINS (1 << HBITS)     // 8192
#define HSHIFT (32 - HBITS)    // 19
#define QCAP 4096              // per-quarter candidate cap
#define CANDCAP 4096

typedef unsigned long long u64;

// ---------------- scratch (static device globals; no allocation) ----------------
__device__ unsigned g_hist4[BS][NQ][NBINS];            // 4 MB, fully overwritten each run
__device__ unsigned g_qcnt[BS][NQ];
__device__ u64      g_qcand[BS][NQ][QCAP];             // 4 MB
__device__ float4   g_boxes[BS][KPRE];
__device__ float    g_scores[BS][KPRE];
__device__ __align__(128) u64 g_mask[BS][KPRE][NWORDS]; // upper-tri overwritten; lower-tri stays 0

// float -> order-preserving uint (ascending)
__device__ __forceinline__ unsigned flip_f(float f) {
    unsigned u = __float_as_uint(f);
    return (u & 0x80000000u) ? ~u : (u | 0x80000000u);
}
__device__ __forceinline__ float unflip_f(unsigned k) {
    unsigned u = (k & 0x80000000u) ? (k ^ 0x80000000u) : ~k;
    return __uint_as_float(u);
}
__device__ __forceinline__ float read_dim(const int* p) {
    int v = *p;
    if (v > 0 && v < (1 << 24)) return (float)v;
    return __int_as_float(v);
}

// =============================================================================
// KA: per-quarter histogram + local threshold + local candidate gather.
// grid (NQ, BS), 1024 threads, 32 KB dynamic smem (histogram).
// Invariant: local threshold bin t_q <= global threshold bin, so the union of
// quarter candidate lists contains every global top-1000 element.
// =============================================================================
extern __shared__ unsigned s_dynA[];

__global__ __launch_bounds__(1024) void local_select_kernel(
    const float* __restrict__ logits)
{
    const int b   = blockIdx.y;
    const int q   = blockIdx.x;
    const int tid = threadIdx.x;

    unsigned* hist = s_dynA;                 // NBINS u32
    __shared__ unsigned s_suf[1024];
    __shared__ unsigned s_t;
    __shared__ unsigned s_cnt;

    const float4* lg4 = (const float4*)(logits + (size_t)b * NANCH);
    const int v0 = q * QVEC;
    const int v1 = v0 + QVEC;

    for (int i = tid; i < NBINS; i += 1024) hist[i] = 0u;
    if (tid == 0) s_cnt = 0u;
    __syncthreads();

    // ---- sweep 1: histogram ----
    for (int i = v0 + tid; i < v1; i += 1024) {
        float4 v = lg4[i];
        atomicAdd(&hist[flip_f(v.x) >> HSHIFT], 1u);
        atomicAdd(&hist[flip_f(v.y) >> HSHIFT], 1u);
        atomicAdd(&hist[flip_f(v.z) >> HSHIFT], 1u);
        atomicAdd(&hist[flip_f(v.w) >> HSHIFT], 1u);
    }
    __syncthreads();

    // ---- write hist slice (plain coalesced stores; no atomics, no zero pass) ----
    for (int i = tid; i < NBINS; i += 1024) g_hist4[b][q][i] = hist[i];

    // ---- local threshold: largest t with local suffix(t) >= KPRE ----
    {
        const int base = tid * (NBINS / 1024);
        unsigned s = 0;
        #pragma unroll
        for (int k = 0; k < NBINS / 1024; ++k) s += hist[base + k];
        s_suf[tid] = s;
        __syncthreads();
        for (int off = 1; off < 1024; off <<= 1) {
            unsigned v = (tid + off < 1024) ? s_suf[tid + off] : 0u;
            __syncthreads();
            s_suf[tid] += v;
            __syncthreads();
        }
        unsigned mine  = s_suf[tid];
        unsigned above = (tid < 1023) ? s_suf[tid + 1] : 0u;
        if (mine >= KPRE && above < KPRE) {
            unsigned acc = above;
            int t = base;
            #pragma unroll
            for (int k = NBINS / 1024 - 1; k >= 0; --k) {
                acc += hist[base + k];
                if (acc >= KPRE) { t = base + k; break; }
            }
            s_t = (unsigned)t;
        }
    }
    __syncthreads();
    const unsigned t = s_t;

    // ---- sweep 2: gather local candidates (data L1/L2-hot from sweep 1) ----
    for (int i = v0 + tid; i < v1; i += 1024) {
        float4 v = lg4[i];
        unsigned k0 = flip_f(v.x);
        unsigned k1 = flip_f(v.y);
        unsigned k2 = flip_f(v.z);
        unsigned k3 = flip_f(v.w);
        const int i0 = 4 * i;
        if ((k0 >> HSHIFT) >= t) {
            unsigned p = atomicAdd(&s_cnt, 1u);
            if (p < QCAP) g_qcand[b][q][p] = ((u64)k0 << 32) | (unsigned)(~(unsigned)(i0));
        }
        if ((k1 >> HSHIFT) >= t) {
            unsigned p = atomicAdd(&s_cnt, 1u);
            if (p < QCAP) g_qcand[b][q][p] = ((u64)k1 << 32) | (unsigned)(~(unsigned)(i0 + 1));
        }
        if ((k2 >> HSHIFT) >= t) {
            unsigned p = atomicAdd(&s_cnt, 1u);
            if (p < QCAP) g_qcand[b][q][p] = ((u64)k2 << 32) | (unsigned)(~(unsigned)(i0 + 2));
        }
        if ((k3 >> HSHIFT) >= t) {
            unsigned p = atomicAdd(&s_cnt, 1u);
            if (p < QCAP) g_qcand[b][q][p] = ((u64)k3 << 32) | (unsigned)(~(unsigned)(i0 + 3));
        }
    }
    __syncthreads();
    if (tid == 0) g_qcnt[b][q] = min(s_cnt, (unsigned)QCAP);
}

// =============================================================================
// KB: sum hist slices -> exact global threshold -> filter quarter candidates
//     -> bitonic sort -> decode+clip top-1000.  grid (BS), 1024 threads.
// =============================================================================
extern __shared__ unsigned s_dynB[];   // aliased: hist u32[NBINS] then cand u64[CANDCAP]

__global__ __launch_bounds__(1024) void global_select_decode(
    const float* __restrict__ deltas,
    const float* __restrict__ anchors,
    const int* __restrict__ p_ih,
    const int* __restrict__ p_iw)
{
    const int b   = blockIdx.x;
    const int tid = threadIdx.x;

    unsigned* hist = s_dynB;
    u64*      cand = (u64*)s_dynB;
    __shared__ unsigned s_suf[1024];
    __shared__ unsigned s_t;
    __shared__ unsigned s_cnt;

    // ---- sum the 4 slices into smem hist ----
    for (int i = tid; i < NBINS; i += 1024) {
        unsigned s = g_hist4[b][0][i] + g_hist4[b][1][i]
                   + g_hist4[b][2][i] + g_hist4[b][3][i];
        hist[i] = s;
    }
    if (tid == 0) s_cnt = 0u;
    __syncthreads();

    // ---- global threshold bin ----
    {
        const int base = tid * (NBINS / 1024);
        unsigned s = 0;
        #pragma unroll
        for (int k = 0; k < NBINS / 1024; ++k) s += hist[base + k];
        s_suf[tid] = s;
        __syncthreads();
        for (int off = 1; off < 1024; off <<= 1) {
            unsigned v = (tid + off < 1024) ? s_suf[tid + off] : 0u;
            __syncthreads();
            s_suf[tid] += v;
            __syncthreads();
        }
        unsigned mine  = s_suf[tid];
        unsigned above = (tid < 1023) ? s_suf[tid + 1] : 0u;
        if (mine >= KPRE && above < KPRE) {
            unsigned acc = above;
            int t = base;
            #pragma unroll
            for (int k = NBINS / 1024 - 1; k >= 0; --k) {
                acc += hist[base + k];
                if (acc >= KPRE) { t = base + k; break; }
            }
            s_t = (unsigned)t;
        }
    }
    __syncthreads();
    const unsigned t = s_t;
    __syncthreads();            // all hist reads done before aliasing to cand

    // ---- filter quarter candidate lists by global threshold ----
    #pragma unroll
    for (int q = 0; q < NQ; ++q) {
        const int nq = (int)g_qcnt[b][q];
        for (int i = tid; i < nq; i += 1024) {
            u64 comp = g_qcand[b][q][i];
            if (((unsigned)(comp >> 32) >> HSHIFT) >= t) {
                unsigned p = atomicAdd(&s_cnt, 1u);
                if (p < CANDCAP) cand[p] = comp;
            }
        }
    }
    __syncthreads();

    const int n = min((int)s_cnt, CANDCAP);
    const int S = (n <= 2048) ? 2048 : CANDCAP;
    for (int i = n + tid; i < S; i += 1024) cand[i] = 0ull;
    __syncthreads();

    // ---- bitonic sort descending ((score desc, idx asc)) ----
    for (int size = 2; size <= S; size <<= 1) {
        for (int stride = size >> 1; stride > 0; stride >>= 1) {
            for (int k = tid; k < (S >> 1); k += 1024) {
                int i = 2 * k - (k & (stride - 1));
                int j = i + stride;
                u64 a = cand[i];
                u64 c = cand[j];
                bool desc = ((i & size) == 0);
                if ((a < c) == desc) { cand[i] = c; cand[j] = a; }
            }
            __syncthreads();
        }
    }

    // ---- decode + clip top-1000 ----
    const float fw = read_dim(p_iw);
    const float fh = read_dim(p_ih);
    if (tid < KPRE) {
        u64 comp = cand[tid];
        unsigned idx = ~(unsigned)(comp & 0xFFFFFFFFull);
        unsigned key = (unsigned)(comp >> 32);
        float logit = unflip_f(key);
        float score = 1.0f / (1.0f + expf(-logit));

        float4 d = ((const float4*)deltas)[(size_t)b * NANCH + idx];
        float4 a = ((const float4*)anchors)[idx];
        float aw  = a.z - a.x;
        float ah  = a.w - a.y;
        float acx = a.x + 0.5f * aw;
        float acy = a.y + 0.5f * ah;
        float cx = d.x * aw + acx;
        float cy = d.y * ah + acy;
        float w  = expf(d.z) * aw;
        float h  = expf(d.w) * ah;
        float x1 = fminf(fmaxf(cx - 0.5f * w, 0.0f), fw);
        float y1 = fminf(fmaxf(cy - 0.5f * h, 0.0f), fh);
        float x2 = fminf(fmaxf(cx + 0.5f * w, 0.0f), fw);
        float y2 = fminf(fmaxf(cy + 0.5f * h, 0.0f), fh);
        g_boxes[b][tid]  = make_float4(x1, y1, x2, y2);
        g_scores[b][tid] = score;
    }
}

// =============================================================================
// K2: IoU bitmask, upper-triangular blocks, divide-free fast path with exact
//     fallback near the decision boundary. grid (136, BS), 64 threads.
// =============================================================================
__global__ __launch_bounds__(64) void nms_mask_kernel()
{
    const int b = blockIdx.y;
    int p = blockIdx.x;
    int rb = 0, rem = NWORDS;
    while (p >= rem) { p -= rem; ++rb; --rem; }
    const int cb = rb + p;
    const int i  = rb * 64 + threadIdx.x;

    __shared__ float4 cbox[64];
    __shared__ float  carea[64];
    const int cbase = cb * 64;
    const int ncol  = min(64, KPRE - cbase);
    if (threadIdx.x < ncol) {
        float4 bx = g_boxes[b][cbase + threadIdx.x];
        cbox[threadIdx.x]  = bx;
        carea[threadIdx.x] = (bx.z - bx.x) * (bx.w - bx.y);
    }
    __syncthreads();
    if (i >= KPRE) return;

    u64 bits = 0ull;
    float4 bi = g_boxes[b][i];
    float  ai = (bi.z - bi.x) * (bi.w - bi.y);
    const int j0 = (i >= cbase) ? (i - cbase + 1) : 0;
    for (int j = j0; j < ncol; ++j) {
        float4 bj = cbox[j];
        float lx = fmaxf(bi.x, bj.x);
        float ly = fmaxf(bi.y, bj.y);
        float rx = fminf(bi.z, bj.z);
        float ry = fminf(bi.w, bj.w);
        float w  = fmaxf(rx - lx, 0.0f);
        float h  = fmaxf(ry - ly, 0.0f);
        float inter = w * h;
        float u = ai + carea[j] - inter + 1e-12f;
        float d = inter - NMS_THR * u;        // sign decides, away from boundary
        bool sup = d > 0.0f;
        if (fabsf(d) <= 1e-4f * u)            // rare: resolve with exact division
            sup = (inter / u) > NMS_THR;
        if (sup) bits |= (1ull << j);
    }
    g_mask[b][i][cb] = bits;
}

// =============================================================================
// K3: sequential greedy scan, register-resident removal mask, LDS.128 rows
// =============================================================================
extern __shared__ u64 s_mask[];   // KPRE*NWORDS u64 = 128 KB

__global__ __launch_bounds__(1024) void nms_scan_out_kernel(float* __restrict__ out)
{
    const int b   = blockIdx.x;
    const int tid = threadIdx.x;

    __shared__ int s_list[KPOST];
    __shared__ int s_kept;

    const ulonglong2* gm2 = (const ulonglong2*)&g_mask[b][0][0];
    ulonglong2* sm2 = (ulonglong2*)s_mask;
    for (int i = tid; i < KPRE * NWORDS / 2; i += 1024) sm2[i] = gm2[i];
    __syncthreads();

    if (tid == 0) {
        u64 remv[NWORDS];
        #pragma unroll
        for (int k = 0; k < NWORDS; ++k) remv[k] = 0ull;
        int kept = 0;
        #pragma unroll
        for (int w = 0; w < NWORDS; ++w) {
            if (kept >= KPOST) break;
            const u64 valid = (w == NWORDS - 1)
                ? ((1ull << (KPRE - 64 * (NWORDS - 1))) - 1ull) : ~0ull;
            u64 avail = (~remv[w]) & valid;
            while (avail) {
                int bit = __ffsll((long long)avail) - 1;
                int i = w * 64 + bit;
                s_list[kept++] = i;
                if (kept == KPOST) break;
                const ulonglong2* row = (const ulonglong2*)&s_mask[i * NWORDS];
                #pragma unroll
                for (int k = 0; k < 8; ++k) {
                    ulonglong2 v = row[k];
                    remv[2 * k]     |= v.x;
                    remv[2 * k + 1] |= v.y;
                }
                u64 high = (bit == 63) ? 0ull : (~0ull << (bit + 1));
                avail = (~remv[w]) & valid & high;
            }
        }
        s_kept = kept;
    }
    __syncthreads();

    const int kept = s_kept;
    float* ob = out + (size_t)b * KPOST * 5;
    for (int r = tid; r < KPOST; r += 1024) {
        if (r < kept) {
            int i = s_list[r];
            float4 bx = g_boxes[b][i];
            float  sc = g_scores[b][i];
            ob[r * 5 + 0] = bx.x;
            ob[r * 5 + 1] = bx.y;
            ob[r * 5 + 2] = bx.z;
            ob[r * 5 + 3] = bx.w;
            ob[r * 5 + 4] = sc;
        } else {
            ob[r * 5 + 0] = 0.0f;
            ob[r * 5 + 1] = 0.0f;
            ob[r * 5 + 2] = 0.0f;
            ob[r * 5 + 3] = 0.0f;
            ob[r * 5 + 4] = 0.0f;
        }
    }
}

// =============================================================================
extern "C" void kernel_launch(void* const* d_in, const int* in_sizes, int n_in,
                              void* d_out, int out_size)
{
    const float* logits  = (const float*)d_in[0];
    const float* deltas  = (const float*)d_in[1];
    const float* anchors = (const float*)d_in[2];
    const int*   p_ih    = (const int*)d_in[3];
    const int*   p_iw    = (const int*)d_in[4];

    cudaFuncSetAttribute(local_select_kernel,
                         cudaFuncAttributeMaxDynamicSharedMemorySize,
                         NBINS * (int)sizeof(unsigned));
    cudaFuncSetAttribute(global_select_decode,
                         cudaFuncAttributeMaxDynamicSharedMemorySize,
                         CANDCAP * (int)sizeof(u64));
    cudaFuncSetAttribute(nms_scan_out_kernel,
                         cudaFuncAttributeMaxDynamicSharedMemorySize,
                         KPRE * NWORDS * (int)sizeof(u64));

    local_select_kernel<<<dim3(NQ, BS), 1024, NBINS * sizeof(unsigned)>>>(logits);
    global_select_decode<<<BS, 1024, CANDCAP * sizeof(u64)>>>(
        deltas, anchors, p_ih, p_iw);
    nms_mask_kernel<<<dim3(NWORDS * (NWORDS + 1) / 2, BS), 64>>>();
    nms_scan_out_kernel<<<BS, 1024, KPRE * NWORDS * sizeof(u64)>>>((float*)d_out);
}